// round 1
// baseline (speedup 1.0000x reference)
#include <cuda_runtime.h>

#define NUM_B 2
#define SEQ   2048
#define DIM   1024
#define NH    16
#define HD    64
#define M_ROWS (NUM_B*SEQ)      // 4096
#define N_QKV  (3*DIM)          // 3072

// Scratch (static device allocations — allowed; cudaMalloc is not)
__device__ float g_q[(size_t)NUM_B*NH*SEQ*HD];
__device__ float g_k[(size_t)NUM_B*NH*SEQ*HD];
__device__ float g_v[(size_t)NUM_B*NH*SEQ*HD];
__device__ float g_att[(size_t)M_ROWS*DIM];

// ---------------------------------------------------------------------------
// GEMM1: qkv = x @ W_qkv + b_qkv, scattered into g_q/g_k/g_v as [B,H,S,Hd]
// 128x128 tile, BK=16, 256 threads, 8x8 register tile per thread.
// ---------------------------------------------------------------------------
__global__ __launch_bounds__(256) void qkv_gemm(const float* __restrict__ A,
                                                const float* __restrict__ Bw,
                                                const float* __restrict__ bias) {
    __shared__ float As[16][132];   // A transposed: As[k][m]
    __shared__ float Bs[16][128];
    const int t  = threadIdx.x;
    const int tx = t & 15, ty = t >> 4;
    const int m0 = blockIdx.y * 128, n0 = blockIdx.x * 128;
    float acc[8][8] = {};

    for (int k0 = 0; k0 < DIM; k0 += 16) {
        #pragma unroll
        for (int i = 0; i < 2; i++) {
            int li  = t + i * 256;                 // 0..511
            int row = li >> 2, c4 = (li & 3) << 2; // A tile 128x16
            float4 va = *(const float4*)(A + (size_t)(m0 + row) * DIM + k0 + c4);
            As[c4+0][row] = va.x; As[c4+1][row] = va.y;
            As[c4+2][row] = va.z; As[c4+3][row] = va.w;
            int rowb = li >> 5, cb = (li & 31) << 2; // B tile 16x128
            *(float4*)&Bs[rowb][cb] =
                *(const float4*)(Bw + (size_t)(k0 + rowb) * N_QKV + n0 + cb);
        }
        __syncthreads();
        #pragma unroll
        for (int kk = 0; kk < 16; kk++) {
            float a[8], b[8];
            *(float4*)(a)   = *(float4*)&As[kk][ty*8];
            *(float4*)(a+4) = *(float4*)&As[kk][ty*8+4];
            *(float4*)(b)   = *(float4*)&Bs[kk][tx*8];
            *(float4*)(b+4) = *(float4*)&Bs[kk][tx*8+4];
            #pragma unroll
            for (int i = 0; i < 8; i++)
                #pragma unroll
                for (int j = 0; j < 8; j++)
                    acc[i][j] = fmaf(a[i], b[j], acc[i][j]);
        }
        __syncthreads();
    }

    #pragma unroll
    for (int i = 0; i < 8; i++) {
        int m  = m0 + ty*8 + i;
        int bb = m >> 11;            // batch
        int s  = m & (SEQ - 1);      // seq position
        #pragma unroll
        for (int j = 0; j < 8; j++) {
            int n = n0 + tx*8 + j;
            float v = acc[i][j] + bias[n];
            int h = n / 192, r = n - h * 192;
            int part = r >> 6, d = r & 63;
            size_t idx = (((size_t)(bb*NH + h)) * SEQ + s) * HD + d;
            float* dst = (part == 0) ? g_q : (part == 1) ? g_k : g_v;
            dst[idx] = v;
        }
    }
}

// ---------------------------------------------------------------------------
// Flash attention, fp32. logits = 2*q·k - |k|^2  (the -|q|^2 per-row term
// cancels in softmax). 64 queries x 64 keys per tile, online softmax,
// P tile aliases the K buffer. 256 threads, 4x4 register tiles.
// ---------------------------------------------------------------------------
#define TSTRIDE 68   // 64 + 4 pad, keeps float4 alignment
#define FLASH_SMEM ((3*64*TSTRIDE + 64) * (int)sizeof(float))

__global__ __launch_bounds__(256) void flash_attn() {
    extern __shared__ float sm[];
    float* Qt  = sm;                     // [64][TSTRIDE] : Qt[d][r]
    float* Kt  = sm + 64*TSTRIDE;        // [64][TSTRIDE] : Kt[d][c], reused as Pt[c][r]
    float* Vs  = sm + 2*64*TSTRIDE;      // [64][TSTRIDE] : Vs[t][d]
    float* ksq = sm + 3*64*TSTRIDE;      // [64]

    const int t  = threadIdx.x;
    const int tx = t & 15, ty = t >> 4;
    const int r0 = ty * 4, c0 = tx * 4;
    const int bh = blockIdx.y;
    const int s0 = blockIdx.x * 64;
    const size_t base = (size_t)bh * SEQ * HD;

    // Load Q tile, transposed to d-major
    #pragma unroll
    for (int i = 0; i < 4; i++) {
        int li  = t + i * 256;
        int row = li >> 4, c4 = (li & 15) << 2;
        float4 v = *(const float4*)(g_q + base + (size_t)(s0 + row) * HD + c4);
        Qt[(c4+0)*TSTRIDE + row] = v.x; Qt[(c4+1)*TSTRIDE + row] = v.y;
        Qt[(c4+2)*TSTRIDE + row] = v.z; Qt[(c4+3)*TSTRIDE + row] = v.w;
    }

    float o[4][4] = {};
    float mst[4], lst[4];
    #pragma unroll
    for (int i = 0; i < 4; i++) { mst[i] = -1e30f; lst[i] = 0.f; }

    for (int t0 = 0; t0 < SEQ; t0 += 64) {
        __syncthreads();   // prior-iteration Pt/Vs consumers done
        // Load K (transposed) and V tiles
        #pragma unroll
        for (int i = 0; i < 4; i++) {
            int li  = t + i * 256;
            int row = li >> 4, c4 = (li & 15) << 2;
            float4 kv = *(const float4*)(g_k + base + (size_t)(t0 + row) * HD + c4);
            Kt[(c4+0)*TSTRIDE + row] = kv.x; Kt[(c4+1)*TSTRIDE + row] = kv.y;
            Kt[(c4+2)*TSTRIDE + row] = kv.z; Kt[(c4+3)*TSTRIDE + row] = kv.w;
            float4 vv = *(const float4*)(g_v + base + (size_t)(t0 + row) * HD + c4);
            *(float4*)&Vs[row*TSTRIDE + c4] = vv;
        }
        __syncthreads();
        if (t < 64) {
            float s = 0.f;
            #pragma unroll 16
            for (int d = 0; d < 64; d++) {
                float kv = Kt[d*TSTRIDE + t];
                s = fmaf(kv, kv, s);
            }
            ksq[t] = s;
        }
        __syncthreads();

        // S = Q . K^T   (4x4 register tile per thread)
        float acc[4][4] = {};
        #pragma unroll 16
        for (int d = 0; d < 64; d++) {
            float4 q = *(float4*)&Qt[d*TSTRIDE + r0];
            float4 k = *(float4*)&Kt[d*TSTRIDE + c0];
            acc[0][0] = fmaf(q.x, k.x, acc[0][0]); acc[0][1] = fmaf(q.x, k.y, acc[0][1]);
            acc[0][2] = fmaf(q.x, k.z, acc[0][2]); acc[0][3] = fmaf(q.x, k.w, acc[0][3]);
            acc[1][0] = fmaf(q.y, k.x, acc[1][0]); acc[1][1] = fmaf(q.y, k.y, acc[1][1]);
            acc[1][2] = fmaf(q.y, k.z, acc[1][2]); acc[1][3] = fmaf(q.y, k.w, acc[1][3]);
            acc[2][0] = fmaf(q.z, k.x, acc[2][0]); acc[2][1] = fmaf(q.z, k.y, acc[2][1]);
            acc[2][2] = fmaf(q.z, k.z, acc[2][2]); acc[2][3] = fmaf(q.z, k.w, acc[2][3]);
            acc[3][0] = fmaf(q.w, k.x, acc[3][0]); acc[3][1] = fmaf(q.w, k.y, acc[3][1]);
            acc[3][2] = fmaf(q.w, k.z, acc[3][2]); acc[3][3] = fmaf(q.w, k.w, acc[3][3]);
        }

        float kq[4] = { ksq[c0], ksq[c0+1], ksq[c0+2], ksq[c0+3] };
        float p[4][4];
        #pragma unroll
        for (int i = 0; i < 4; i++) {
            #pragma unroll
            for (int j = 0; j < 4; j++)
                p[i][j] = 2.f * acc[i][j] - kq[j];
            float mx = fmaxf(fmaxf(p[i][0], p[i][1]), fmaxf(p[i][2], p[i][3]));
            #pragma unroll
            for (int off = 8; off; off >>= 1)
                mx = fmaxf(mx, __shfl_xor_sync(0xffffffffu, mx, off));
            float mn = fmaxf(mst[i], mx);
            float al = __expf(mst[i] - mn);
            float rs = 0.f;
            #pragma unroll
            for (int j = 0; j < 4; j++) { p[i][j] = __expf(p[i][j] - mn); rs += p[i][j]; }
            #pragma unroll
            for (int off = 8; off; off >>= 1)
                rs += __shfl_xor_sync(0xffffffffu, rs, off);
            lst[i] = lst[i] * al + rs;
            mst[i] = mn;
            #pragma unroll
            for (int j = 0; j < 4; j++) o[i][j] *= al;
        }

        __syncthreads();   // all threads done reading Kt as K
        #pragma unroll
        for (int i = 0; i < 4; i++)
            #pragma unroll
            for (int j = 0; j < 4; j++)
                Kt[(c0+j)*TSTRIDE + (r0+i)] = p[i][j];   // Pt[key][query]
        __syncthreads();

        // O += P . V
        #pragma unroll 8
        for (int kk = 0; kk < 64; kk++) {
            float4 pv = *(float4*)&Kt[kk*TSTRIDE + r0];
            float4 vv = *(float4*)&Vs[kk*TSTRIDE + c0];
            o[0][0] = fmaf(pv.x, vv.x, o[0][0]); o[0][1] = fmaf(pv.x, vv.y, o[0][1]);
            o[0][2] = fmaf(pv.x, vv.z, o[0][2]); o[0][3] = fmaf(pv.x, vv.w, o[0][3]);
            o[1][0] = fmaf(pv.y, vv.x, o[1][0]); o[1][1] = fmaf(pv.y, vv.y, o[1][1]);
            o[1][2] = fmaf(pv.y, vv.z, o[1][2]); o[1][3] = fmaf(pv.y, vv.w, o[1][3]);
            o[2][0] = fmaf(pv.z, vv.x, o[2][0]); o[2][1] = fmaf(pv.z, vv.y, o[2][1]);
            o[2][2] = fmaf(pv.z, vv.z, o[2][2]); o[2][3] = fmaf(pv.z, vv.w, o[2][3]);
            o[3][0] = fmaf(pv.w, vv.x, o[3][0]); o[3][1] = fmaf(pv.w, vv.y, o[3][1]);
            o[3][2] = fmaf(pv.w, vv.z, o[3][2]); o[3][3] = fmaf(pv.w, vv.w, o[3][3]);
        }
    }

    // Epilogue: normalize, write to g_att in [B,S,D] layout (D = h*64 + d)
    const int b = bh >> 4, h = bh & 15;
    #pragma unroll
    for (int i = 0; i < 4; i++) {
        float inv = 1.f / lst[i];
        int s = s0 + r0 + i;
        #pragma unroll
        for (int j = 0; j < 4; j++)
            g_att[((size_t)(b*SEQ + s)) * DIM + h*HD + c0 + j] = o[i][j] * inv;
    }
}

// ---------------------------------------------------------------------------
// GEMM3: out = g_att @ W_o + b_o
// ---------------------------------------------------------------------------
__global__ __launch_bounds__(256) void out_gemm(const float* __restrict__ Bw,
                                                const float* __restrict__ bias,
                                                float* __restrict__ out) {
    __shared__ float As[16][132];
    __shared__ float Bs[16][128];
    const int t  = threadIdx.x;
    const int tx = t & 15, ty = t >> 4;
    const int m0 = blockIdx.y * 128, n0 = blockIdx.x * 128;
    float acc[8][8] = {};

    for (int k0 = 0; k0 < DIM; k0 += 16) {
        #pragma unroll
        for (int i = 0; i < 2; i++) {
            int li  = t + i * 256;
            int row = li >> 2, c4 = (li & 3) << 2;
            float4 va = *(const float4*)(g_att + (size_t)(m0 + row) * DIM + k0 + c4);
            As[c4+0][row] = va.x; As[c4+1][row] = va.y;
            As[c4+2][row] = va.z; As[c4+3][row] = va.w;
            int rowb = li >> 5, cb = (li & 31) << 2;
            *(float4*)&Bs[rowb][cb] =
                *(const float4*)(Bw + (size_t)(k0 + rowb) * DIM + n0 + cb);
        }
        __syncthreads();
        #pragma unroll
        for (int kk = 0; kk < 16; kk++) {
            float a[8], b[8];
            *(float4*)(a)   = *(float4*)&As[kk][ty*8];
            *(float4*)(a+4) = *(float4*)&As[kk][ty*8+4];
            *(float4*)(b)   = *(float4*)&Bs[kk][tx*8];
            *(float4*)(b+4) = *(float4*)&Bs[kk][tx*8+4];
            #pragma unroll
            for (int i = 0; i < 8; i++)
                #pragma unroll
                for (int j = 0; j < 8; j++)
                    acc[i][j] = fmaf(a[i], b[j], acc[i][j]);
        }
        __syncthreads();
    }

    #pragma unroll
    for (int i = 0; i < 8; i++) {
        int m = m0 + ty*8 + i;
        #pragma unroll
        for (int j = 0; j < 8; j++) {
            int n = n0 + tx*8 + j;
            out[(size_t)m * DIM + n] = acc[i][j] + bias[n];
        }
    }
}

// ---------------------------------------------------------------------------
extern "C" void kernel_launch(void* const* d_in, const int* in_sizes, int n_in,
                              void* d_out, int out_size) {
    (void)in_sizes; (void)n_in; (void)out_size;
    const float* x     = (const float*)d_in[0];
    const float* Wqkv  = (const float*)d_in[1];
    const float* bqkv  = (const float*)d_in[2];
    const float* Wo    = (const float*)d_in[3];
    const float* bo    = (const float*)d_in[4];
    float*       out   = (float*)d_out;

    qkv_gemm<<<dim3(N_QKV/128, M_ROWS/128), 256>>>(x, Wqkv, bqkv);

    cudaFuncSetAttribute(flash_attn, cudaFuncAttributeMaxDynamicSharedMemorySize,
                         FLASH_SMEM);
    flash_attn<<<dim3(SEQ/64, NUM_B*NH), 256, FLASH_SMEM>>>();

    out_gemm<<<dim3(DIM/128, M_ROWS/128), 256>>>(Wo, bo, out);
}

// round 3
// speedup vs baseline: 1.0974x; 1.0974x over previous
#include <cuda_runtime.h>
#include <cstdint>

#define NUM_B 2
#define SEQ   2048
#define DIM   1024
#define NH    16
#define HD    64
#define M_ROWS (NUM_B*SEQ)      // 4096
#define N_QKV  (3*DIM)          // 3072
#define KDIM   DIM              // 1024
#define KCHUNK 32
#define NCHUNK (KDIM/KCHUNK)    // 32

// Scratch (static device arrays — no runtime allocation)
__device__ float g_q  [(size_t)NUM_B*NH*SEQ*HD];
__device__ float g_k  [(size_t)NUM_B*NH*SEQ*HD];
__device__ float g_v  [(size_t)NUM_B*NH*SEQ*HD];
__device__ float g_att[(size_t)M_ROWS*DIM];
__device__ float g_wqt[(size_t)N_QKV*KDIM];   // W_qkv^T  [3072][1024]
__device__ float g_wot[(size_t)DIM*KDIM];     // W_o^T    [1024][1024]

// ---------------------------------------------------------------------------
// Helpers: tf32 rounding, mma.sync, cp.async  (all sm_80-baseline PTX)
// ---------------------------------------------------------------------------
__device__ __forceinline__ uint32_t tf32_bits(float x) {
    float r;
    asm("cvt.rna.tf32.f32 %0, %1;" : "=f"(r) : "f"(x));
    return __float_as_uint(r);
}
__device__ __forceinline__ void split_tf32(float x, uint32_t& hi, uint32_t& lo) {
    float h;
    asm("cvt.rna.tf32.f32 %0, %1;" : "=f"(h) : "f"(x));
    hi = __float_as_uint(h);
    float l;
    asm("cvt.rna.tf32.f32 %0, %1;" : "=f"(l) : "f"(x - h));
    lo = __float_as_uint(l);
}
__device__ __forceinline__ void mma_tf32(float* d,
                                         uint32_t a0, uint32_t a1, uint32_t a2, uint32_t a3,
                                         uint32_t b0, uint32_t b1) {
    asm volatile(
        "mma.sync.aligned.m16n8k8.row.col.f32.tf32.tf32.f32 "
        "{%0,%1,%2,%3}, {%4,%5,%6,%7}, {%8,%9}, {%0,%1,%2,%3};"
        : "+f"(d[0]), "+f"(d[1]), "+f"(d[2]), "+f"(d[3])
        : "r"(a0), "r"(a1), "r"(a2), "r"(a3), "r"(b0), "r"(b1));
}
#define CP16(dst, src) \
    asm volatile("cp.async.cg.shared.global [%0], [%1], 16;" :: "r"(dst), "l"(src))
#define CP_COMMIT() asm volatile("cp.async.commit_group;" ::: "memory")
#define CP_WAIT1()  asm volatile("cp.async.wait_group 1;" ::: "memory")
#define CP_WAIT0()  asm volatile("cp.async.wait_group 0;" ::: "memory")

__device__ __forceinline__ uint32_t smem_u32(const void* p) {
    uint32_t a;
    asm("{ .reg .u64 t; cvta.to.shared.u64 t, %1; cvt.u32.u64 %0, t; }"
        : "=r"(a) : "l"(p));
    return a;
}

// ---------------------------------------------------------------------------
// Weight transpose: src[R][C] -> dst[C][R]
// ---------------------------------------------------------------------------
__global__ void transpose32(const float* __restrict__ src, float* __restrict__ dst,
                            int R, int C) {
    __shared__ float t[32][33];
    int bx = blockIdx.x * 32, by = blockIdx.y * 32;
    int x = threadIdx.x, y = threadIdx.y;
    #pragma unroll
    for (int i = 0; i < 32; i += 8)
        t[y + i][x] = src[(size_t)(by + y + i) * C + bx + x];
    __syncthreads();
    #pragma unroll
    for (int i = 0; i < 32; i += 8)
        dst[(size_t)(bx + y + i) * R + by + x] = t[x][y + i];
}

// ---------------------------------------------------------------------------
// 3xTF32 mma.sync GEMM: C[m,n] = A[m,:].Bt[n,:] + bias[n]
// 128x128 block tile, K-chunk 32, double-buffered cp.async.
// 8 warps in 4(M) x 2(N) grid; warp tile 32x64 (2 m-tiles x 8 n-tiles).
// mode 0: scatter into g_q/g_k/g_v. mode 1: direct write to outp.
// ---------------------------------------------------------------------------
#define TSTR   36                 // smem row stride (floats): conflict-free quads
#define TILE_F (128*TSTR)         // 4608 floats per operand tile
#define GSMEM  (4*TILE_F*(int)sizeof(float))   // 73728 B

__global__ __launch_bounds__(256) void tf32_gemm(
    const float* __restrict__ A,    // [M][K] row-major
    const float* __restrict__ Bt,   // [N][K] row-major
    const float* __restrict__ bias,
    float* __restrict__ outp, int mode)
{
    extern __shared__ float smf[];
    const int t   = threadIdx.x;
    const int wid = t >> 5, lane = t & 31;
    const int qr  = lane >> 2, qc = lane & 3;
    const int m0  = blockIdx.y * 128, n0 = blockIdx.x * 128;
    const int wm  = (wid & 3) * 32;     // warp row offset
    const int wn  = (wid >> 2) * 64;    // warp col offset

    const uint32_t sbase = smem_u32(smf);
    const int ldrow = t >> 3;           // 0..31
    const int ldk4  = (t & 7) * 4;      // float offset within chunk row

    float acc[2][8][4];
    #pragma unroll
    for (int i = 0; i < 2; i++)
        #pragma unroll
        for (int j = 0; j < 8; j++)
            #pragma unroll
            for (int e = 0; e < 4; e++) acc[i][j][e] = 0.f;

    // async load of one K-chunk into buffer buf
    auto load_chunk = [&](int c, int buf) {
        const int k0 = c * KCHUNK;
        const uint32_t ab = sbase + (uint32_t)(buf * 2 * TILE_F) * 4;
        const uint32_t bb = ab + (uint32_t)TILE_F * 4;
        #pragma unroll
        for (int i = 0; i < 4; i++) {
            const int row = ldrow + i * 32;
            CP16(ab + (uint32_t)(row * TSTR + ldk4) * 4,
                 A  + (size_t)(m0 + row) * KDIM + k0 + ldk4);
            CP16(bb + (uint32_t)(row * TSTR + ldk4) * 4,
                 Bt + (size_t)(n0 + row) * KDIM + k0 + ldk4);
        }
    };

    load_chunk(0, 0);
    CP_COMMIT();

    for (int c = 0; c < NCHUNK; c++) {
        const int buf = c & 1;
        if (c + 1 < NCHUNK) {
            load_chunk(c + 1, buf ^ 1);
            CP_COMMIT();
            CP_WAIT1();
        } else {
            CP_WAIT0();
        }
        __syncthreads();

        const float* As = smf + buf * 2 * TILE_F;
        const float* Bs = As + TILE_F;

        #pragma unroll
        for (int ks = 0; ks < 4; ks++) {
            const int kk = ks * 8;
            // A fragments (2 m-tiles), split hi/lo
            uint32_t ah[2][4], al[2][4];
            #pragma unroll
            for (int tm = 0; tm < 2; tm++) {
                const int mr = wm + tm * 16 + qr;
                split_tf32(As[(mr    ) * TSTR + kk + qc    ], ah[tm][0], al[tm][0]);
                split_tf32(As[(mr + 8) * TSTR + kk + qc    ], ah[tm][1], al[tm][1]);
                split_tf32(As[(mr    ) * TSTR + kk + qc + 4], ah[tm][2], al[tm][2]);
                split_tf32(As[(mr + 8) * TSTR + kk + qc + 4], ah[tm][3], al[tm][3]);
            }
            // B fragments (8 n-tiles), split hi/lo
            uint32_t bh[8][2], bl[8][2];
            #pragma unroll
            for (int tn = 0; tn < 8; tn++) {
                const int nr = wn + tn * 8 + qr;
                split_tf32(Bs[nr * TSTR + kk + qc    ], bh[tn][0], bl[tn][0]);
                split_tf32(Bs[nr * TSTR + kk + qc + 4], bh[tn][1], bl[tn][1]);
            }
            #pragma unroll
            for (int tm = 0; tm < 2; tm++)
                #pragma unroll
                for (int tn = 0; tn < 8; tn++) {
                    float* d = acc[tm][tn];
                    mma_tf32(d, ah[tm][0], ah[tm][1], ah[tm][2], ah[tm][3],
                             bh[tn][0], bh[tn][1]);
                    mma_tf32(d, ah[tm][0], ah[tm][1], ah[tm][2], ah[tm][3],
                             bl[tn][0], bl[tn][1]);
                    mma_tf32(d, al[tm][0], al[tm][1], al[tm][2], al[tm][3],
                             bh[tn][0], bh[tn][1]);
                }
        }
        __syncthreads();
    }

    // Epilogue
    #pragma unroll
    for (int tm = 0; tm < 2; tm++) {
        const int r0 = m0 + wm + tm * 16 + qr;
        #pragma unroll
        for (int tn = 0; tn < 8; tn++) {
            const int col = n0 + wn + tn * 8 + qc * 2;
            const float bz0 = bias[col], bz1 = bias[col + 1];
            #pragma unroll
            for (int half = 0; half < 2; half++) {
                const int row = r0 + half * 8;
                const float v0 = acc[tm][tn][half * 2 + 0] + bz0;
                const float v1 = acc[tm][tn][half * 2 + 1] + bz1;
                if (mode == 0) {
                    const int bb = row >> 11, s = row & (SEQ - 1);
                    const int h = col / 192, r = col - h * 192;
                    const int part = r >> 6, dd = r & 63;
                    float* dst = (part == 0) ? g_q : (part == 1) ? g_k : g_v;
                    float2 w = make_float2(v0, v1);
                    *(float2*)&dst[(((size_t)(bb * NH + h)) * SEQ + s) * HD + dd] = w;
                } else {
                    float2 w = make_float2(v0, v1);
                    *(float2*)&outp[(size_t)row * DIM + col] = w;
                }
            }
        }
    }
}

// ---------------------------------------------------------------------------
// Flash attention, fp32 (unchanged, known-good). logits = 2*q.k - |k|^2.
// ---------------------------------------------------------------------------
#define TSTRIDE 68
#define FLASH_SMEM ((3*64*TSTRIDE + 64) * (int)sizeof(float))

__global__ __launch_bounds__(256) void flash_attn() {
    extern __shared__ float smf[];
    float* Qt  = smf;
    float* Kt  = smf + 64*TSTRIDE;
    float* Vs  = smf + 2*64*TSTRIDE;
    float* ksq = smf + 3*64*TSTRIDE;

    const int t  = threadIdx.x;
    const int tx = t & 15, ty = t >> 4;
    const int r0 = ty * 4, c0 = tx * 4;
    const int bh = blockIdx.y;
    const int s0 = blockIdx.x * 64;
    const size_t base = (size_t)bh * SEQ * HD;

    #pragma unroll
    for (int i = 0; i < 4; i++) {
        int li  = t + i * 256;
        int row = li >> 4, c4 = (li & 15) << 2;
        float4 v = *(const float4*)(g_q + base + (size_t)(s0 + row) * HD + c4);
        Qt[(c4+0)*TSTRIDE + row] = v.x; Qt[(c4+1)*TSTRIDE + row] = v.y;
        Qt[(c4+2)*TSTRIDE + row] = v.z; Qt[(c4+3)*TSTRIDE + row] = v.w;
    }

    float o[4][4] = {};
    float mst[4], lst[4];
    #pragma unroll
    for (int i = 0; i < 4; i++) { mst[i] = -1e30f; lst[i] = 0.f; }

    for (int t0 = 0; t0 < SEQ; t0 += 64) {
        __syncthreads();
        #pragma unroll
        for (int i = 0; i < 4; i++) {
            int li  = t + i * 256;
            int row = li >> 4, c4 = (li & 15) << 2;
            float4 kv = *(const float4*)(g_k + base + (size_t)(t0 + row) * HD + c4);
            Kt[(c4+0)*TSTRIDE + row] = kv.x; Kt[(c4+1)*TSTRIDE + row] = kv.y;
            Kt[(c4+2)*TSTRIDE + row] = kv.z; Kt[(c4+3)*TSTRIDE + row] = kv.w;
            float4 vv = *(const float4*)(g_v + base + (size_t)(t0 + row) * HD + c4);
            *(float4*)&Vs[row*TSTRIDE + c4] = vv;
        }
        __syncthreads();
        if (t < 64) {
            float s = 0.f;
            #pragma unroll 16
            for (int d = 0; d < 64; d++) {
                float kv = Kt[d*TSTRIDE + t];
                s = fmaf(kv, kv, s);
            }
            ksq[t] = s;
        }
        __syncthreads();

        float acc[4][4] = {};
        #pragma unroll 16
        for (int d = 0; d < 64; d++) {
            float4 q = *(float4*)&Qt[d*TSTRIDE + r0];
            float4 k = *(float4*)&Kt[d*TSTRIDE + c0];
            acc[0][0] = fmaf(q.x, k.x, acc[0][0]); acc[0][1] = fmaf(q.x, k.y, acc[0][1]);
            acc[0][2] = fmaf(q.x, k.z, acc[0][2]); acc[0][3] = fmaf(q.x, k.w, acc[0][3]);
            acc[1][0] = fmaf(q.y, k.x, acc[1][0]); acc[1][1] = fmaf(q.y, k.y, acc[1][1]);
            acc[1][2] = fmaf(q.y, k.z, acc[1][2]); acc[1][3] = fmaf(q.y, k.w, acc[1][3]);
            acc[2][0] = fmaf(q.z, k.x, acc[2][0]); acc[2][1] = fmaf(q.z, k.y, acc[2][1]);
            acc[2][2] = fmaf(q.z, k.z, acc[2][2]); acc[2][3] = fmaf(q.z, k.w, acc[2][3]);
            acc[3][0] = fmaf(q.w, k.x, acc[3][0]); acc[3][1] = fmaf(q.w, k.y, acc[3][1]);
            acc[3][2] = fmaf(q.w, k.z, acc[3][2]); acc[3][3] = fmaf(q.w, k.w, acc[3][3]);
        }

        float kq[4] = { ksq[c0], ksq[c0+1], ksq[c0+2], ksq[c0+3] };
        float p[4][4];
        #pragma unroll
        for (int i = 0; i < 4; i++) {
            #pragma unroll
            for (int j = 0; j < 4; j++)
                p[i][j] = 2.f * acc[i][j] - kq[j];
            float mx = fmaxf(fmaxf(p[i][0], p[i][1]), fmaxf(p[i][2], p[i][3]));
            #pragma unroll
            for (int off = 8; off; off >>= 1)
                mx = fmaxf(mx, __shfl_xor_sync(0xffffffffu, mx, off));
            float mn = fmaxf(mst[i], mx);
            float al = __expf(mst[i] - mn);
            float rs = 0.f;
            #pragma unroll
            for (int j = 0; j < 4; j++) { p[i][j] = __expf(p[i][j] - mn); rs += p[i][j]; }
            #pragma unroll
            for (int off = 8; off; off >>= 1)
                rs += __shfl_xor_sync(0xffffffffu, rs, off);
            lst[i] = lst[i] * al + rs;
            mst[i] = mn;
            #pragma unroll
            for (int j = 0; j < 4; j++) o[i][j] *= al;
        }

        __syncthreads();
        #pragma unroll
        for (int i = 0; i < 4; i++)
            #pragma unroll
            for (int j = 0; j < 4; j++)
                Kt[(c0+j)*TSTRIDE + (r0+i)] = p[i][j];
        __syncthreads();

        #pragma unroll 8
        for (int kk = 0; kk < 64; kk++) {
            float4 pv = *(float4*)&Kt[kk*TSTRIDE + r0];
            float4 vv = *(float4*)&Vs[kk*TSTRIDE + c0];
            o[0][0] = fmaf(pv.x, vv.x, o[0][0]); o[0][1] = fmaf(pv.x, vv.y, o[0][1]);
            o[0][2] = fmaf(pv.x, vv.z, o[0][2]); o[0][3] = fmaf(pv.x, vv.w, o[0][3]);
            o[1][0] = fmaf(pv.y, vv.x, o[1][0]); o[1][1] = fmaf(pv.y, vv.y, o[1][1]);
            o[1][2] = fmaf(pv.y, vv.z, o[1][2]); o[1][3] = fmaf(pv.y, vv.w, o[1][3]);
            o[2][0] = fmaf(pv.z, vv.x, o[2][0]); o[2][1] = fmaf(pv.z, vv.y, o[2][1]);
            o[2][2] = fmaf(pv.z, vv.z, o[2][2]); o[2][3] = fmaf(pv.z, vv.w, o[2][3]);
            o[3][0] = fmaf(pv.w, vv.x, o[3][0]); o[3][1] = fmaf(pv.w, vv.y, o[3][1]);
            o[3][2] = fmaf(pv.w, vv.z, o[3][2]); o[3][3] = fmaf(pv.w, vv.w, o[3][3]);
        }
    }

    const int b = bh >> 4, h = bh & 15;
    #pragma unroll
    for (int i = 0; i < 4; i++) {
        float inv = 1.f / lst[i];
        int s = s0 + r0 + i;
        #pragma unroll
        for (int j = 0; j < 4; j++)
            g_att[((size_t)(b*SEQ + s)) * DIM + h*HD + c0 + j] = o[i][j] * inv;
    }
}

// ---------------------------------------------------------------------------
extern "C" void kernel_launch(void* const* d_in, const int* in_sizes, int n_in,
                              void* d_out, int out_size) {
    (void)in_sizes; (void)n_in; (void)out_size;
    const float* x    = (const float*)d_in[0];
    const float* Wqkv = (const float*)d_in[1];
    const float* bqkv = (const float*)d_in[2];
    const float* Wo   = (const float*)d_in[3];
    const float* bo   = (const float*)d_in[4];
    float*       out  = (float*)d_out;

    float* wqt; cudaGetSymbolAddress((void**)&wqt, g_wqt);
    float* wot; cudaGetSymbolAddress((void**)&wot, g_wot);
    float* att; cudaGetSymbolAddress((void**)&att, g_att);

    cudaFuncSetAttribute(tf32_gemm, cudaFuncAttributeMaxDynamicSharedMemorySize, GSMEM);
    cudaFuncSetAttribute(flash_attn, cudaFuncAttributeMaxDynamicSharedMemorySize, FLASH_SMEM);

    transpose32<<<dim3(N_QKV/32, KDIM/32), dim3(32, 8)>>>(Wqkv, wqt, KDIM, N_QKV);
    transpose32<<<dim3(DIM/32,  KDIM/32), dim3(32, 8)>>>(Wo,   wot, KDIM, DIM);

    tf32_gemm<<<dim3(N_QKV/128, M_ROWS/128), 256, GSMEM>>>(x, wqt, bqkv, nullptr, 0);

    flash_attn<<<dim3(SEQ/64, NUM_B*NH), 256, FLASH_SMEM>>>();

    tf32_gemm<<<dim3(DIM/128, M_ROWS/128), 256, GSMEM>>>(att, wot, bo, out, 1);
}

// round 4
// speedup vs baseline: 1.2846x; 1.1706x over previous
#include <cuda_runtime.h>
#include <cstdint>

#define NUM_B 2
#define SEQ   2048
#define DIM   1024
#define NH    16
#define HD    64
#define M_ROWS (NUM_B*SEQ)      // 4096
#define N_QKV  (3*DIM)          // 3072
#define KDIM   DIM              // 1024
#define KCHUNK 32
#define NCHUNK (KDIM/KCHUNK)    // 32

// Scratch (static device arrays — no runtime allocation)
__device__ float g_q  [(size_t)NUM_B*NH*SEQ*HD];
__device__ float g_k  [(size_t)NUM_B*NH*SEQ*HD];
__device__ float g_v  [(size_t)NUM_B*NH*SEQ*HD];
__device__ float g_att[(size_t)M_ROWS*DIM];
__device__ float g_wqt[(size_t)N_QKV*KDIM];   // W_qkv^T  [3072][1024]
__device__ float g_wot[(size_t)DIM*KDIM];     // W_o^T    [1024][1024]

// ---------------------------------------------------------------------------
// Helpers (all sm_80-baseline PTX; validated in R3)
// ---------------------------------------------------------------------------
__device__ __forceinline__ float tf32f(float x) {
    float r;
    asm("cvt.rna.tf32.f32 %0, %1;" : "=f"(r) : "f"(x));
    return r;
}
__device__ __forceinline__ void split2(float x, float& h, float& l) {
    asm("cvt.rna.tf32.f32 %0, %1;" : "=f"(h) : "f"(x));
    float r = x - h;
    asm("cvt.rna.tf32.f32 %0, %1;" : "=f"(l) : "f"(r));
}
__device__ __forceinline__ void split_tf32(float x, uint32_t& hi, uint32_t& lo) {
    float h, l;
    split2(x, h, l);
    hi = __float_as_uint(h);
    lo = __float_as_uint(l);
}
__device__ __forceinline__ void mma_tf32(float* d,
                                         uint32_t a0, uint32_t a1, uint32_t a2, uint32_t a3,
                                         uint32_t b0, uint32_t b1) {
    asm volatile(
        "mma.sync.aligned.m16n8k8.row.col.f32.tf32.tf32.f32 "
        "{%0,%1,%2,%3}, {%4,%5,%6,%7}, {%8,%9}, {%0,%1,%2,%3};"
        : "+f"(d[0]), "+f"(d[1]), "+f"(d[2]), "+f"(d[3])
        : "r"(a0), "r"(a1), "r"(a2), "r"(a3), "r"(b0), "r"(b1));
}
#define CP16(dst, src) \
    asm volatile("cp.async.cg.shared.global [%0], [%1], 16;" :: "r"(dst), "l"(src))
#define CP_COMMIT() asm volatile("cp.async.commit_group;" ::: "memory")
#define CP_WAIT1()  asm volatile("cp.async.wait_group 1;" ::: "memory")
#define CP_WAIT0()  asm volatile("cp.async.wait_group 0;" ::: "memory")

__device__ __forceinline__ uint32_t smem_u32(const void* p) {
    uint32_t a;
    asm("{ .reg .u64 t; cvta.to.shared.u64 t, %1; cvt.u32.u64 %0, t; }"
        : "=r"(a) : "l"(p));
    return a;
}

// ---------------------------------------------------------------------------
// Weight transpose: src[R][C] -> dst[C][R]
// ---------------------------------------------------------------------------
__global__ void transpose32(const float* __restrict__ src, float* __restrict__ dst,
                            int R, int C) {
    __shared__ float t[32][33];
    int bx = blockIdx.x * 32, by = blockIdx.y * 32;
    int x = threadIdx.x, y = threadIdx.y;
    #pragma unroll
    for (int i = 0; i < 32; i += 8)
        t[y + i][x] = src[(size_t)(by + y + i) * C + bx + x];
    __syncthreads();
    #pragma unroll
    for (int i = 0; i < 32; i += 8)
        dst[(size_t)(bx + y + i) * R + by + x] = t[x][y + i];
}

// ---------------------------------------------------------------------------
// 3xTF32 mma.sync GEMM (unchanged from R3, known-good)
// ---------------------------------------------------------------------------
#define TSTR   36
#define TILE_F (128*TSTR)
#define GSMEM  (4*TILE_F*(int)sizeof(float))

__global__ __launch_bounds__(256) void tf32_gemm(
    const float* __restrict__ A,
    const float* __restrict__ Bt,
    const float* __restrict__ bias,
    float* __restrict__ outp, int mode)
{
    extern __shared__ float smf[];
    const int t   = threadIdx.x;
    const int wid = t >> 5, lane = t & 31;
    const int qr  = lane >> 2, qc = lane & 3;
    const int m0  = blockIdx.y * 128, n0 = blockIdx.x * 128;
    const int wm  = (wid & 3) * 32;
    const int wn  = (wid >> 2) * 64;

    const uint32_t sbase = smem_u32(smf);
    const int ldrow = t >> 3;
    const int ldk4  = (t & 7) * 4;

    float acc[2][8][4];
    #pragma unroll
    for (int i = 0; i < 2; i++)
        #pragma unroll
        for (int j = 0; j < 8; j++)
            #pragma unroll
            for (int e = 0; e < 4; e++) acc[i][j][e] = 0.f;

    auto load_chunk = [&](int c, int buf) {
        const int k0 = c * KCHUNK;
        const uint32_t ab = sbase + (uint32_t)(buf * 2 * TILE_F) * 4;
        const uint32_t bb = ab + (uint32_t)TILE_F * 4;
        #pragma unroll
        for (int i = 0; i < 4; i++) {
            const int row = ldrow + i * 32;
            CP16(ab + (uint32_t)(row * TSTR + ldk4) * 4,
                 A  + (size_t)(m0 + row) * KDIM + k0 + ldk4);
            CP16(bb + (uint32_t)(row * TSTR + ldk4) * 4,
                 Bt + (size_t)(n0 + row) * KDIM + k0 + ldk4);
        }
    };

    load_chunk(0, 0);
    CP_COMMIT();

    for (int c = 0; c < NCHUNK; c++) {
        const int buf = c & 1;
        if (c + 1 < NCHUNK) {
            load_chunk(c + 1, buf ^ 1);
            CP_COMMIT();
            CP_WAIT1();
        } else {
            CP_WAIT0();
        }
        __syncthreads();

        const float* As = smf + buf * 2 * TILE_F;
        const float* Bs = As + TILE_F;

        #pragma unroll
        for (int ks = 0; ks < 4; ks++) {
            const int kk = ks * 8;
            uint32_t ah[2][4], al[2][4];
            #pragma unroll
            for (int tm = 0; tm < 2; tm++) {
                const int mr = wm + tm * 16 + qr;
                split_tf32(As[(mr    ) * TSTR + kk + qc    ], ah[tm][0], al[tm][0]);
                split_tf32(As[(mr + 8) * TSTR + kk + qc    ], ah[tm][1], al[tm][1]);
                split_tf32(As[(mr    ) * TSTR + kk + qc + 4], ah[tm][2], al[tm][2]);
                split_tf32(As[(mr + 8) * TSTR + kk + qc + 4], ah[tm][3], al[tm][3]);
            }
            uint32_t bh[8][2], bl[8][2];
            #pragma unroll
            for (int tn = 0; tn < 8; tn++) {
                const int nr = wn + tn * 8 + qr;
                split_tf32(Bs[nr * TSTR + kk + qc    ], bh[tn][0], bl[tn][0]);
                split_tf32(Bs[nr * TSTR + kk + qc + 4], bh[tn][1], bl[tn][1]);
            }
            #pragma unroll
            for (int tm = 0; tm < 2; tm++)
                #pragma unroll
                for (int tn = 0; tn < 8; tn++) {
                    float* d = acc[tm][tn];
                    mma_tf32(d, ah[tm][0], ah[tm][1], ah[tm][2], ah[tm][3],
                             bh[tn][0], bh[tn][1]);
                    mma_tf32(d, ah[tm][0], ah[tm][1], ah[tm][2], ah[tm][3],
                             bl[tn][0], bl[tn][1]);
                    mma_tf32(d, al[tm][0], al[tm][1], al[tm][2], al[tm][3],
                             bh[tn][0], bh[tn][1]);
                }
        }
        __syncthreads();
    }

    #pragma unroll
    for (int tm = 0; tm < 2; tm++) {
        const int r0 = m0 + wm + tm * 16 + qr;
        #pragma unroll
        for (int tn = 0; tn < 8; tn++) {
            const int col = n0 + wn + tn * 8 + qc * 2;
            const float bz0 = bias[col], bz1 = bias[col + 1];
            #pragma unroll
            for (int half = 0; half < 2; half++) {
                const int row = r0 + half * 8;
                const float v0 = acc[tm][tn][half * 2 + 0] + bz0;
                const float v1 = acc[tm][tn][half * 2 + 1] + bz1;
                if (mode == 0) {
                    const int bb = row >> 11, s = row & (SEQ - 1);
                    const int h = col / 192, r = col - h * 192;
                    const int part = r >> 6, dd = r & 63;
                    float* dst = (part == 0) ? g_q : (part == 1) ? g_k : g_v;
                    float2 w = make_float2(v0, v1);
                    *(float2*)&dst[(((size_t)(bb * NH + h)) * SEQ + s) * HD + dd] = w;
                } else {
                    float2 w = make_float2(v0, v1);
                    *(float2*)&outp[(size_t)row * DIM + col] = w;
                }
            }
        }
    }
}

// ---------------------------------------------------------------------------
// Flash attention on mma.sync tf32.
// 64 queries/CTA, 4 warps (16 rows each), 64-key tiles.
// logits = (2q).k - |k|^2 ; QK^T in 3xTF32, PV in 1xTF32.
// smem: Qh, Ql, Kh(=Ps after S-loop), Kl, Vt — stride 68 (banks 4qr+qc, clean)
// ---------------------------------------------------------------------------
#define FSTR 68
#define FT   (64*FSTR)                 // 4352 floats per tile
#define FLASH_SMEM ((5*FT + 64)*(int)sizeof(float))   // 87296 B

__global__ __launch_bounds__(128) void flash_mma() {
    extern __shared__ float s[];
    float* Qh  = s;
    float* Ql  = s + FT;
    float* Kh  = s + 2*FT;      // aliased as Ps after the S-loop
    float* Kl  = s + 3*FT;
    float* Vt  = s + 4*FT;      // transposed V: Vt[d][t]
    float* ksq = s + 5*FT;
    float* Ps  = Kh;

    const int t = threadIdx.x, lane = t & 31, w = t >> 5;
    const int qr = lane >> 2, qc = lane & 3;
    const int wm = w * 16;
    const int bh = blockIdx.y;
    const int s0 = blockIdx.x * 64;
    const size_t base = (size_t)bh * SEQ * HD;

    // Load Q tile (x2 folded in), split hi/lo
    #pragma unroll
    for (int i = 0; i < 8; i++) {
        int li  = t + i * 128;
        int row = li >> 4, c4 = (li & 15) << 2;
        float4 v = *(const float4*)(g_q + base + (size_t)(s0 + row) * HD + c4);
        float h0, l0, h1, l1, h2, l2, h3, l3;
        split2(2.f * v.x, h0, l0); split2(2.f * v.y, h1, l1);
        split2(2.f * v.z, h2, l2); split2(2.f * v.w, h3, l3);
        float* qh = Qh + row * FSTR + c4;
        float* ql = Ql + row * FSTR + c4;
        qh[0] = h0; qh[1] = h1; qh[2] = h2; qh[3] = h3;
        ql[0] = l0; ql[1] = l1; ql[2] = l2; ql[3] = l3;
    }

    float oacc[8][4];
    #pragma unroll
    for (int tn = 0; tn < 8; tn++)
        #pragma unroll
        for (int e = 0; e < 4; e++) oacc[tn][e] = 0.f;
    float m0r = -1e30f, m1r = -1e30f, l0r = 0.f, l1r = 0.f;

    for (int t0 = 0; t0 < SEQ; t0 += 64) {
        __syncthreads();   // prior-iter consumers of Kh(Ps)/Kl/Vt done
        // Load K (split hi/lo) and V (tf32-rounded, transposed)
        #pragma unroll
        for (int i = 0; i < 8; i++) {
            int li  = t + i * 128;
            int row = li >> 4, c4 = (li & 15) << 2;
            float4 kv = *(const float4*)(g_k + base + (size_t)(t0 + row) * HD + c4);
            float h0, l0, h1, l1, h2, l2, h3, l3;
            split2(kv.x, h0, l0); split2(kv.y, h1, l1);
            split2(kv.z, h2, l2); split2(kv.w, h3, l3);
            float* kh = Kh + row * FSTR + c4;
            float* kl = Kl + row * FSTR + c4;
            kh[0] = h0; kh[1] = h1; kh[2] = h2; kh[3] = h3;
            kl[0] = l0; kl[1] = l1; kl[2] = l2; kl[3] = l3;
            float4 vv = *(const float4*)(g_v + base + (size_t)(t0 + row) * HD + c4);
            Vt[(c4+0)*FSTR + row] = tf32f(vv.x);
            Vt[(c4+1)*FSTR + row] = tf32f(vv.y);
            Vt[(c4+2)*FSTR + row] = tf32f(vv.z);
            Vt[(c4+3)*FSTR + row] = tf32f(vv.w);
        }
        __syncthreads();

        // ksq[key] = |k|^2 (reconstruct k = kh + kl, exact to ~2^-22)
        {
            const int key = t >> 1, dh = (t & 1) * 32;
            float ss = 0.f;
            #pragma unroll
            for (int j = 0; j < 8; j++) {
                float4 h4 = *(float4*)&Kh[key * FSTR + dh + j * 4];
                float4 l4 = *(float4*)&Kl[key * FSTR + dh + j * 4];
                float k0 = h4.x + l4.x, k1 = h4.y + l4.y;
                float k2 = h4.z + l4.z, k3 = h4.w + l4.w;
                ss = fmaf(k0, k0, ss); ss = fmaf(k1, k1, ss);
                ss = fmaf(k2, k2, ss); ss = fmaf(k3, k3, ss);
            }
            ss += __shfl_xor_sync(0xffffffffu, ss, 1);
            if (!(t & 1)) ksq[key] = ss;
        }
        __syncthreads();

        // S = (2Q).K^T  (3xTF32)
        float sacc[8][4];
        #pragma unroll
        for (int tn = 0; tn < 8; tn++)
            #pragma unroll
            for (int e = 0; e < 4; e++) sacc[tn][e] = 0.f;

        #pragma unroll
        for (int ks = 0; ks < 8; ks++) {
            const int kk = ks * 8;
            const float* qhp = Qh + (wm + qr) * FSTR + kk + qc;
            const float* qlp = Ql + (wm + qr) * FSTR + kk + qc;
            uint32_t ah0 = __float_as_uint(qhp[0]);
            uint32_t ah1 = __float_as_uint(qhp[8*FSTR]);
            uint32_t ah2 = __float_as_uint(qhp[4]);
            uint32_t ah3 = __float_as_uint(qhp[8*FSTR + 4]);
            uint32_t al0 = __float_as_uint(qlp[0]);
            uint32_t al1 = __float_as_uint(qlp[8*FSTR]);
            uint32_t al2 = __float_as_uint(qlp[4]);
            uint32_t al3 = __float_as_uint(qlp[8*FSTR + 4]);
            #pragma unroll
            for (int tn = 0; tn < 8; tn++) {
                const float* khp = Kh + (tn*8 + qr) * FSTR + kk + qc;
                const float* klp = Kl + (tn*8 + qr) * FSTR + kk + qc;
                uint32_t bh0 = __float_as_uint(khp[0]);
                uint32_t bh1 = __float_as_uint(khp[4]);
                uint32_t bl0 = __float_as_uint(klp[0]);
                uint32_t bl1 = __float_as_uint(klp[4]);
                mma_tf32(sacc[tn], ah0, ah1, ah2, ah3, bh0, bh1);
                mma_tf32(sacc[tn], ah0, ah1, ah2, ah3, bl0, bl1);
                mma_tf32(sacc[tn], al0, al1, al2, al3, bh0, bh1);
            }
        }

        __syncthreads();   // all warps done reading Kh — safe to alias as Ps

        // Softmax (rows qr and qr+8 of this warp's 16)
        float mx0 = -1e30f, mx1 = -1e30f;
        #pragma unroll
        for (int tn = 0; tn < 8; tn++) {
            const float k0 = ksq[tn*8 + 2*qc], k1 = ksq[tn*8 + 2*qc + 1];
            sacc[tn][0] -= k0; sacc[tn][1] -= k1;
            sacc[tn][2] -= k0; sacc[tn][3] -= k1;
            mx0 = fmaxf(mx0, fmaxf(sacc[tn][0], sacc[tn][1]));
            mx1 = fmaxf(mx1, fmaxf(sacc[tn][2], sacc[tn][3]));
        }
        #pragma unroll
        for (int off = 1; off <= 2; off <<= 1) {
            mx0 = fmaxf(mx0, __shfl_xor_sync(0xffffffffu, mx0, off));
            mx1 = fmaxf(mx1, __shfl_xor_sync(0xffffffffu, mx1, off));
        }
        const float mn0 = fmaxf(m0r, mx0), mn1 = fmaxf(m1r, mx1);
        const float a0 = __expf(m0r - mn0), a1 = __expf(m1r - mn1);
        m0r = mn0; m1r = mn1;

        float rs0 = 0.f, rs1 = 0.f;
        #pragma unroll
        for (int tn = 0; tn < 8; tn++) {
            const float p0 = __expf(sacc[tn][0] - mn0);
            const float p1 = __expf(sacc[tn][1] - mn0);
            const float p2 = __expf(sacc[tn][2] - mn1);
            const float p3 = __expf(sacc[tn][3] - mn1);
            rs0 += p0 + p1; rs1 += p2 + p3;
            *(float2*)&Ps[(wm + qr    ) * FSTR + tn*8 + 2*qc] =
                make_float2(tf32f(p0), tf32f(p1));
            *(float2*)&Ps[(wm + qr + 8) * FSTR + tn*8 + 2*qc] =
                make_float2(tf32f(p2), tf32f(p3));
        }
        #pragma unroll
        for (int off = 1; off <= 2; off <<= 1) {
            rs0 += __shfl_xor_sync(0xffffffffu, rs0, off);
            rs1 += __shfl_xor_sync(0xffffffffu, rs1, off);
        }
        l0r = l0r * a0 + rs0;
        l1r = l1r * a1 + rs1;
        #pragma unroll
        for (int tn = 0; tn < 8; tn++) {
            oacc[tn][0] *= a0; oacc[tn][1] *= a0;
            oacc[tn][2] *= a1; oacc[tn][3] *= a1;
        }
        __syncwarp();   // Ps rows are warp-private; order STS before LDS

        // O += P.V  (1xTF32)
        #pragma unroll
        for (int ks = 0; ks < 8; ks++) {
            const int kk = ks * 8;
            const float* pp = Ps + (wm + qr) * FSTR + kk + qc;
            uint32_t a0f = __float_as_uint(pp[0]);
            uint32_t a1f = __float_as_uint(pp[8*FSTR]);
            uint32_t a2f = __float_as_uint(pp[4]);
            uint32_t a3f = __float_as_uint(pp[8*FSTR + 4]);
            #pragma unroll
            for (int tn = 0; tn < 8; tn++) {
                const float* vp = Vt + (tn*8 + qr) * FSTR + kk + qc;
                mma_tf32(oacc[tn], a0f, a1f, a2f, a3f,
                         __float_as_uint(vp[0]), __float_as_uint(vp[4]));
            }
        }
    }

    // Epilogue: normalize, write g_att[B,S,D] (D = h*64 + d)
    const float inv0 = 1.f / l0r, inv1 = 1.f / l1r;
    const int b = bh >> 4, h = bh & 15;
    const int row0 = s0 + wm + qr, row1 = row0 + 8;
    #pragma unroll
    for (int tn = 0; tn < 8; tn++) {
        const int col = h * HD + tn*8 + 2*qc;
        *(float2*)&g_att[(size_t)(b*SEQ + row0) * DIM + col] =
            make_float2(oacc[tn][0] * inv0, oacc[tn][1] * inv0);
        *(float2*)&g_att[(size_t)(b*SEQ + row1) * DIM + col] =
            make_float2(oacc[tn][2] * inv1, oacc[tn][3] * inv1);
    }
}

// ---------------------------------------------------------------------------
extern "C" void kernel_launch(void* const* d_in, const int* in_sizes, int n_in,
                              void* d_out, int out_size) {
    (void)in_sizes; (void)n_in; (void)out_size;
    const float* x    = (const float*)d_in[0];
    const float* Wqkv = (const float*)d_in[1];
    const float* bqkv = (const float*)d_in[2];
    const float* Wo   = (const float*)d_in[3];
    const float* bo   = (const float*)d_in[4];
    float*       out  = (float*)d_out;

    float* wqt; cudaGetSymbolAddress((void**)&wqt, g_wqt);
    float* wot; cudaGetSymbolAddress((void**)&wot, g_wot);
    float* att; cudaGetSymbolAddress((void**)&att, g_att);

    cudaFuncSetAttribute(tf32_gemm, cudaFuncAttributeMaxDynamicSharedMemorySize, GSMEM);
    cudaFuncSetAttribute(flash_mma, cudaFuncAttributeMaxDynamicSharedMemorySize, FLASH_SMEM);

    transpose32<<<dim3(N_QKV/32, KDIM/32), dim3(32, 8)>>>(Wqkv, wqt, KDIM, N_QKV);
    transpose32<<<dim3(DIM/32,  KDIM/32), dim3(32, 8)>>>(Wo,   wot, KDIM, DIM);

    tf32_gemm<<<dim3(N_QKV/128, M_ROWS/128), 256, GSMEM>>>(x, wqt, bqkv, nullptr, 0);

    flash_mma<<<dim3(SEQ/64, NUM_B*NH), 128, FLASH_SMEM>>>();

    tf32_gemm<<<dim3(DIM/128, M_ROWS/128), 256, GSMEM>>>(att, wot, bo, out, 1);
}